// round 6
// baseline (speedup 1.0000x reference)
#include <cuda_runtime.h>

// ---------------------------------------------------------------------------
// SpatialGCN fused pipeline, fp32 SIMT baseline.
// Shapes: B=64, L=243, J=17, D_IN=D_OUT=256.  R = B*L*J = 264384 rows.
// adj is exactly symmetric => adj^T agg == adj agg => fuse w1/w2 into Ws.
// ---------------------------------------------------------------------------

#define NFRM   15552                     // B*L
#define R_ROWS (NFRM * 17)               // 264384
#define R_PAD  264448                    // 2066 * 128 (GEMM tile-aligned)
#define STATS_CHUNK 512
#define NB_STATS ((R_ROWS + STATS_CHUNK - 1) / STATS_CHUNK)  // 517

// Scratch (static device globals; no runtime allocation).
__device__ float g_xa[(size_t)R_PAD * 256];    // aggregated input
__device__ float g_h [(size_t)R_PAD * 256];    // post-GCN hidden (then hn in place)
__device__ float g_mid[(size_t)R_PAD * 512];   // MLP hidden
__device__ float g_Ws[256 * 256];              // w1 + w2
__device__ float g_biasJ[17 * 256];            // aggregated per-joint bias
__device__ float g_psum[NB_STATS * 256];
__device__ float g_pss [NB_STATS * 256];
__device__ float g_scale[256];                 // folded BN scale
__device__ float g_shift[256];                 // folded BN shift

// ---------------------------------------------------------------------------
// prep: Ws = w1 + w2 ; biasJ[i][c] = colsum_i(adj)*b1[c] + rowsum_i(adj)*b2[c]
// ---------------------------------------------------------------------------
__global__ void prep_kernel(const float* __restrict__ w1, const float* __restrict__ w2,
                            const float* __restrict__ b1, const float* __restrict__ b2,
                            const float* __restrict__ adj)
{
    int tid = threadIdx.x;
    for (int i = tid; i < 256 * 256; i += 256)
        g_Ws[i] = w1[i] + w2[i];

    __shared__ float c1[17], c2[17];
    if (tid < 17) {
        float s1 = 0.f, s2 = 0.f;
        #pragma unroll
        for (int j = 0; j < 17; j++) {
            s1 += adj[j * 17 + tid];   // column sum (adj^T agg of b1)
            s2 += adj[tid * 17 + j];   // row sum    (adj   agg of b2)
        }
        c1[tid] = s1; c2[tid] = s2;
    }
    __syncthreads();
    #pragma unroll
    for (int i = 0; i < 17; i++)
        g_biasJ[i * 256 + tid] = c1[i] * b1[tid] + c2[i] * b2[tid];
}

// ---------------------------------------------------------------------------
// agg: xa[n,i,:] = sum_j adj[i,j] * x[n,j,:]   (one block per frame)
// ---------------------------------------------------------------------------
__global__ void agg2_kernel(const float* __restrict__ x, const float* __restrict__ adj)
{
    __shared__ float xs[17][256];
    __shared__ float adjS[17][17];
    const int n = blockIdx.x;
    const int c = threadIdx.x;

    const float* xp = x + (size_t)n * 17 * 256;
    #pragma unroll
    for (int j = 0; j < 17; j++) xs[j][c] = xp[j * 256 + c];
    // FIX (R4): 289 elements, 256 threads -> strided loop (was `if (c<289)`,
    // which left adjS[15][1..16] / adjS[16][*] uninitialized -> rel_err 0.39).
    for (int idx = c; idx < 289; idx += 256)
        adjS[idx / 17][idx % 17] = adj[idx];
    __syncthreads();

    float* xo = g_xa + (size_t)n * 17 * 256;
    #pragma unroll
    for (int i = 0; i < 17; i++) {
        float s = 0.f;
        #pragma unroll
        for (int j = 0; j < 17; j++) s += adjS[i][j] * xs[j][c];
        xo[i * 256 + c] = s;
    }
}

// ---------------------------------------------------------------------------
// Tiled fp32 GEMM: C[M,N] = epi(A[M,K] @ B[N,K]^T + bias)
//   MODE 0: A=g_xa  B=g_Ws   C=g_h   bias=g_biasJ[(row%17)*256+col], ReLU
//   MODE 1: A=g_h   B=param  C=g_mid bias=bias[col],                 ReLU
//   MODE 2: A=g_mid B=param  C=param bias=bias[col], store iff row<R_ROWS
// BM=BN=128, BK=16, 256 threads, 8x8 per-thread microtile.
// ---------------------------------------------------------------------------
template <int MODE>
__global__ void __launch_bounds__(256)
gemm_kernel(const float* __restrict__ Bp, const float* __restrict__ biasp,
            float* __restrict__ Cp)
{
    constexpr int N = (MODE == 1) ? 512 : 256;
    constexpr int K = (MODE == 2) ? 512 : 256;

    const float* __restrict__ A =
        (MODE == 0) ? g_xa : (MODE == 1) ? g_h : g_mid;
    const float* __restrict__ B = (MODE == 0) ? g_Ws : Bp;
    float* __restrict__ C = (MODE == 0) ? g_h : (MODE == 1) ? g_mid : Cp;
    const float* __restrict__ bias = (MODE == 0) ? g_biasJ : biasp;

    __shared__ float As[16][132];
    __shared__ float Bs[16][132];

    const int tid  = threadIdx.x;
    const int tCol = tid & 15;       // 0..15
    const int tRow = tid >> 4;       // 0..15
    const size_t aBase = (size_t)blockIdx.y * 128 * K;
    const size_t bBase = (size_t)blockIdx.x * 128 * K;

    const int lr0 = tid >> 2;        // 0..63
    const int lk  = (tid & 3) * 4;   // 0,4,8,12

    float acc[8][8];
    #pragma unroll
    for (int i = 0; i < 8; i++)
        #pragma unroll
        for (int j = 0; j < 8; j++) acc[i][j] = 0.f;

    #pragma unroll 2
    for (int kt = 0; kt < K; kt += 16) {
        float4 a0 = *(const float4*)&A[aBase + (size_t)lr0 * K + kt + lk];
        float4 a1 = *(const float4*)&A[aBase + (size_t)(lr0 + 64) * K + kt + lk];
        float4 b0 = *(const float4*)&B[bBase + (size_t)lr0 * K + kt + lk];
        float4 b1 = *(const float4*)&B[bBase + (size_t)(lr0 + 64) * K + kt + lk];

        As[lk + 0][lr0] = a0.x; As[lk + 1][lr0] = a0.y;
        As[lk + 2][lr0] = a0.z; As[lk + 3][lr0] = a0.w;
        As[lk + 0][lr0 + 64] = a1.x; As[lk + 1][lr0 + 64] = a1.y;
        As[lk + 2][lr0 + 64] = a1.z; As[lk + 3][lr0 + 64] = a1.w;
        Bs[lk + 0][lr0] = b0.x; Bs[lk + 1][lr0] = b0.y;
        Bs[lk + 2][lr0] = b0.z; Bs[lk + 3][lr0] = b0.w;
        Bs[lk + 0][lr0 + 64] = b1.x; Bs[lk + 1][lr0 + 64] = b1.y;
        Bs[lk + 2][lr0 + 64] = b1.z; Bs[lk + 3][lr0 + 64] = b1.w;
        __syncthreads();

        #pragma unroll
        for (int k = 0; k < 16; k++) {
            float4 m0 = *(const float4*)&As[k][tRow * 8];
            float4 m1 = *(const float4*)&As[k][tRow * 8 + 4];
            float4 n0 = *(const float4*)&Bs[k][tCol * 8];
            float4 n1 = *(const float4*)&Bs[k][tCol * 8 + 4];
            float rm[8] = {m0.x, m0.y, m0.z, m0.w, m1.x, m1.y, m1.z, m1.w};
            float rn[8] = {n0.x, n0.y, n0.z, n0.w, n1.x, n1.y, n1.z, n1.w};
            #pragma unroll
            for (int i = 0; i < 8; i++)
                #pragma unroll
                for (int j = 0; j < 8; j++)
                    acc[i][j] += rm[i] * rn[j];
        }
        __syncthreads();
    }

    const int rowBase = blockIdx.y * 128 + tRow * 8;
    const int colBase = blockIdx.x * 128 + tCol * 8;
    #pragma unroll
    for (int i = 0; i < 8; i++) {
        const int row = rowBase + i;
        if (MODE == 2 && row >= R_ROWS) break;
        const float* bp = (MODE == 0) ? (bias + (row % 17) * 256) : bias;
        #pragma unroll
        for (int j = 0; j < 8; j += 4) {
            float4 v;
            v.x = acc[i][j + 0] + bp[colBase + j + 0];
            v.y = acc[i][j + 1] + bp[colBase + j + 1];
            v.z = acc[i][j + 2] + bp[colBase + j + 2];
            v.w = acc[i][j + 3] + bp[colBase + j + 3];
            if (MODE < 2) {
                v.x = fmaxf(v.x, 0.f); v.y = fmaxf(v.y, 0.f);
                v.z = fmaxf(v.z, 0.f); v.w = fmaxf(v.w, 0.f);
            }
            *(float4*)&C[(size_t)row * N + colBase + j] = v;
        }
    }
}

// ---------------------------------------------------------------------------
// BN stats: deterministic two-stage per-channel sum / sumsq.
// ---------------------------------------------------------------------------
__global__ void stats_kernel()
{
    const int c = threadIdx.x;
    size_t r0 = (size_t)blockIdx.x * STATS_CHUNK;
    size_t r1 = r0 + STATS_CHUNK;
    if (r1 > R_ROWS) r1 = R_ROWS;
    float s = 0.f, ss = 0.f;
    #pragma unroll 4
    for (size_t r = r0; r < r1; r++) {
        float v = g_h[r * 256 + c];
        s += v; ss += v * v;
    }
    g_psum[blockIdx.x * 256 + c] = s;
    g_pss [blockIdx.x * 256 + c] = ss;
}

__global__ void finalize_kernel(const float* __restrict__ bn_gamma,
                                const float* __restrict__ bn_beta)
{
    const int c = threadIdx.x;
    float s = 0.f, ss = 0.f;
    for (int b = 0; b < NB_STATS; b++) {
        s  += g_psum[b * 256 + c];
        ss += g_pss [b * 256 + c];
    }
    const float inv = 1.f / (float)R_ROWS;
    float mean = s * inv;
    float var  = ss * inv - mean * mean;
    float sc = bn_gamma[c] * rsqrtf(var + 1e-5f);
    g_scale[c] = sc;
    g_shift[c] = bn_beta[c] - mean * sc;
}

// ---------------------------------------------------------------------------
// norm: BN affine + LayerNorm, warp per row, in place on g_h.
// ---------------------------------------------------------------------------
__global__ void norm_kernel(const float* __restrict__ ln_g,
                            const float* __restrict__ ln_b)
{
    const int row  = blockIdx.x * 8 + (threadIdx.x >> 5);
    const int lane = threadIdx.x & 31;
    if (row >= R_ROWS) return;
    float* rp = g_h + (size_t)row * 256;
    const int c0 = lane * 8;

    float4 v0 = *(float4*)&rp[c0];
    float4 v1 = *(float4*)&rp[c0 + 4];
    float4 s0 = *(const float4*)&g_scale[c0];
    float4 s1 = *(const float4*)&g_scale[c0 + 4];
    float4 h0 = *(const float4*)&g_shift[c0];
    float4 h1 = *(const float4*)&g_shift[c0 + 4];

    float w[8];
    w[0] = v0.x * s0.x + h0.x; w[1] = v0.y * s0.y + h0.y;
    w[2] = v0.z * s0.z + h0.z; w[3] = v0.w * s0.w + h0.w;
    w[4] = v1.x * s1.x + h1.x; w[5] = v1.y * s1.y + h1.y;
    w[6] = v1.z * s1.z + h1.z; w[7] = v1.w * s1.w + h1.w;

    float sum = 0.f, ssq = 0.f;
    #pragma unroll
    for (int i = 0; i < 8; i++) { sum += w[i]; ssq += w[i] * w[i]; }
    #pragma unroll
    for (int o = 16; o > 0; o >>= 1) {
        sum += __shfl_xor_sync(0xFFFFFFFFu, sum, o);
        ssq += __shfl_xor_sync(0xFFFFFFFFu, ssq, o);
    }
    const float mean = sum * (1.f / 256.f);
    const float var  = ssq * (1.f / 256.f) - mean * mean;
    const float rs   = rsqrtf(var + 1e-5f);

    float4 g0 = *(const float4*)&ln_g[c0];
    float4 g1 = *(const float4*)&ln_g[c0 + 4];
    float4 t0 = *(const float4*)&ln_b[c0];
    float4 t1 = *(const float4*)&ln_b[c0 + 4];
    float gg[8] = {g0.x, g0.y, g0.z, g0.w, g1.x, g1.y, g1.z, g1.w};
    float bb[8] = {t0.x, t0.y, t0.z, t0.w, t1.x, t1.y, t1.z, t1.w};

    float4 o0, o1;
    float* op0 = &o0.x; float* op1 = &o1.x;
    #pragma unroll
    for (int i = 0; i < 4; i++) op0[i] = (w[i] - mean) * rs * gg[i] + bb[i];
    #pragma unroll
    for (int i = 0; i < 4; i++) op1[i] = (w[4 + i] - mean) * rs * gg[4 + i] + bb[4 + i];
    *(float4*)&rp[c0]     = o0;
    *(float4*)&rp[c0 + 4] = o1;
}

// ---------------------------------------------------------------------------
// launch
// ---------------------------------------------------------------------------
extern "C" void kernel_launch(void* const* d_in, const int* in_sizes, int n_in,
                              void* d_out, int out_size)
{
    const float* x    = (const float*)d_in[0];
    const float* adj  = (const float*)d_in[1];
    const float* w1   = (const float*)d_in[2];
    const float* b1   = (const float*)d_in[3];
    const float* w2   = (const float*)d_in[4];
    const float* b2   = (const float*)d_in[5];
    const float* bn_g = (const float*)d_in[6];
    const float* bn_b = (const float*)d_in[7];
    const float* ln_g = (const float*)d_in[8];
    const float* ln_b = (const float*)d_in[9];
    const float* mw1  = (const float*)d_in[10];
    const float* mb1  = (const float*)d_in[11];
    const float* mw2  = (const float*)d_in[12];
    const float* mb2  = (const float*)d_in[13];
    float* out = (float*)d_out;

    prep_kernel<<<1, 256>>>(w1, w2, b1, b2, adj);
    agg2_kernel<<<NFRM, 256>>>(x, adj);

    dim3 g1(256 / 128, R_PAD / 128);           // (2, 2066)
    gemm_kernel<0><<<g1, 256>>>(nullptr, nullptr, nullptr);

    stats_kernel<<<NB_STATS, 256>>>();
    finalize_kernel<<<1, 256>>>(bn_g, bn_b);
    norm_kernel<<<(R_ROWS + 7) / 8, 256>>>(ln_g, ln_b);

    dim3 g2(512 / 128, R_PAD / 128);           // (4, 2066)
    gemm_kernel<1><<<g2, 256>>>(mw1, mb1, nullptr);

    dim3 g3(256 / 128, R_PAD / 128);           // (2, 2066)
    gemm_kernel<2><<<g3, 256>>>(mw2, mb2, out);
}

// round 8
// speedup vs baseline: 3.6812x; 3.6812x over previous
#include <cuda_runtime.h>
#include <cuda_bf16.h>
#include <cstdint>

// ---------------------------------------------------------------------------
// SpatialGCN fused pipeline — mma.sync (HMMA) split-bf16 GEMMs.
// Target is base sm_103 (no tcgen05 -- "a"-features unavailable in this build).
// C = A @ B^T with A,B split into bf16 hi/lo; 3 passes Ah*Bh + Ah*Bl + Al*Bh
// accumulated in fp32 register fragments.
// ---------------------------------------------------------------------------

#define NFRM   15552
#define R_ROWS (NFRM * 17)               // 264384
#define R_PAD  264448                    // 2066 * 128
#define MTILES (R_PAD / 128)             // 2066
#define STATS_CHUNK 512
#define NB_STATS ((R_ROWS + STATS_CHUNK - 1) / STATS_CHUNK)  // 517

// ---- scratch (static device globals, zero-initialized) ----
__device__ __nv_bfloat16 g_xah[(size_t)R_PAD * 256];
__device__ __nv_bfloat16 g_xal[(size_t)R_PAD * 256];
__device__ float         g_h  [(size_t)R_PAD * 256];
__device__ __nv_bfloat16 g_hh [(size_t)R_PAD * 256];
__device__ __nv_bfloat16 g_hl [(size_t)R_PAD * 256];
__device__ __nv_bfloat16 g_midh[(size_t)R_PAD * 512];
__device__ __nv_bfloat16 g_midl[(size_t)R_PAD * 512];
__device__ __nv_bfloat16 g_Wh1[256 * 256], g_Wl1[256 * 256];   // (w1+w2)
__device__ __nv_bfloat16 g_Wh2[512 * 256], g_Wl2[512 * 256];   // mlp_w1
__device__ __nv_bfloat16 g_Wh3[256 * 512], g_Wl3[256 * 512];   // mlp_w2
__device__ float g_biasJ[17 * 256];
__device__ float g_psum[NB_STATS * 256];
__device__ float g_pss [NB_STATS * 256];
__device__ float g_scale[256];
__device__ float g_shift[256];

// ---------------------------------------------------------------------------
// helpers
// ---------------------------------------------------------------------------
__device__ __forceinline__ uint32_t smem_u32(const void* p) {
    uint32_t a;
    asm("{ .reg .u64 t; cvta.to.shared.u64 t, %1; cvt.u32.u64 %0, t; }"
        : "=r"(a) : "l"(p));
    return a;
}
#define CP16(dst, src) \
    asm volatile("cp.async.cg.shared.global [%0], [%1], 16;" :: "r"(dst), "l"(src))
#define CP_COMMIT() asm volatile("cp.async.commit_group;" ::: "memory")
#define CP_WAIT2()  asm volatile("cp.async.wait_group 2;" ::: "memory")

__device__ __forceinline__ void ldsm4(uint32_t* r, uint32_t a) {
    asm volatile("ldmatrix.sync.aligned.m8n8.x4.shared.b16 {%0,%1,%2,%3}, [%4];"
        : "=r"(r[0]), "=r"(r[1]), "=r"(r[2]), "=r"(r[3]) : "r"(a));
}
__device__ __forceinline__ void mma16816(float* d, const uint32_t* a, const uint32_t* b) {
    asm volatile("mma.sync.aligned.m16n8k16.row.col.f32.bf16.bf16.f32 "
        "{%0,%1,%2,%3}, {%4,%5,%6,%7}, {%8,%9}, {%0,%1,%2,%3};"
        : "+f"(d[0]), "+f"(d[1]), "+f"(d[2]), "+f"(d[3])
        : "r"(a[0]), "r"(a[1]), "r"(a[2]), "r"(a[3]), "r"(b[0]), "r"(b[1]));
}
__device__ __forceinline__ uint32_t pack_bf2(float a, float b) {
    __nv_bfloat162 t = __floats2bfloat162_rn(a, b);
    return *reinterpret_cast<uint32_t*>(&t);
}

// ---------------------------------------------------------------------------
// prep: split weights into bf16 hi/lo; aggregated per-joint bias
// ---------------------------------------------------------------------------
__global__ void prep_w_kernel(const float* __restrict__ w1, const float* __restrict__ w2,
                              const float* __restrict__ mw1, const float* __restrict__ mw2)
{
    int i0 = blockIdx.x * blockDim.x + threadIdx.x;
    int st = gridDim.x * blockDim.x;
    for (int t = i0; t < 256 * 256; t += st) {
        float v = w1[t] + w2[t];
        __nv_bfloat16 h = __float2bfloat16(v);
        g_Wh1[t] = h; g_Wl1[t] = __float2bfloat16(v - __bfloat162float(h));
    }
    for (int t = i0; t < 512 * 256; t += st) {
        float v = mw1[t];
        __nv_bfloat16 h = __float2bfloat16(v);
        g_Wh2[t] = h; g_Wl2[t] = __float2bfloat16(v - __bfloat162float(h));
    }
    for (int t = i0; t < 256 * 512; t += st) {
        float v = mw2[t];
        __nv_bfloat16 h = __float2bfloat16(v);
        g_Wh3[t] = h; g_Wl3[t] = __float2bfloat16(v - __bfloat162float(h));
    }
}

__global__ void prep_bias_kernel(const float* __restrict__ b1, const float* __restrict__ b2,
                                 const float* __restrict__ adj)
{
    int tid = threadIdx.x;
    __shared__ float c1[17], c2[17];
    if (tid < 17) {
        float s1 = 0.f, s2 = 0.f;
        #pragma unroll
        for (int j = 0; j < 17; j++) { s1 += adj[j * 17 + tid]; s2 += adj[tid * 17 + j]; }
        c1[tid] = s1; c2[tid] = s2;
    }
    __syncthreads();
    #pragma unroll
    for (int i = 0; i < 17; i++)
        g_biasJ[i * 256 + tid] = c1[i] * b1[tid] + c2[i] * b2[tid];
}

// ---------------------------------------------------------------------------
// agg: xa[n,i,:] = sum_j adj[i,j] x[n,j,:]  -> split bf16 hi/lo
// ---------------------------------------------------------------------------
__global__ void agg_kernel(const float* __restrict__ x, const float* __restrict__ adj)
{
    __shared__ float xs[17][256];
    __shared__ float adjS[17][17];
    const int n = blockIdx.x;
    const int c = threadIdx.x;

    const float* xp = x + (size_t)n * 17 * 256;
    #pragma unroll
    for (int j = 0; j < 17; j++) xs[j][c] = xp[j * 256 + c];
    for (int idx = c; idx < 289; idx += 256)
        adjS[idx / 17][idx % 17] = adj[idx];
    __syncthreads();

    const size_t base = (size_t)n * 17 * 256 + c;
    #pragma unroll
    for (int i = 0; i < 17; i++) {
        float s = 0.f;
        #pragma unroll
        for (int j = 0; j < 17; j++) s += adjS[i][j] * xs[j][c];
        __nv_bfloat16 h = __float2bfloat16(s);
        g_xah[base + i * 256] = h;
        g_xal[base + i * 256] = __float2bfloat16(s - __bfloat162float(h));
    }
}

// ---------------------------------------------------------------------------
// HMMA GEMM: C[128x128 tile] = A @ B^T, split-bf16 (3 passes), cp.async 3-stage.
//  MODE 0: A=xa  (K=256) B=Ws  -> g_h fp32 (+biasJ[row%17], ReLU)
//  MODE 1: A=h   (K=256) B=mw1 -> g_mid hi/lo (+mb1, ReLU), C stride 512
//  MODE 2: A=mid (K=512) B=mw2 -> out fp32 (+mb2), row-guarded
// smem per stage: Ah 16K | Al 16K | Bh 16K | Bl 16K  = 64K; 3 stages.
// ---------------------------------------------------------------------------
template <int MODE>
__global__ void __launch_bounds__(256, 1)
hmma_gemm_kernel(const float* __restrict__ biasp, float* __restrict__ Cp)
{
    constexpr int K   = (MODE == 2) ? 512 : 256;
    constexpr int NKC = K / 64;
    constexpr int CST = (MODE == 1) ? 512 : 256;     // C row stride
    const __nv_bfloat16* __restrict__ Ah = (MODE == 0) ? g_xah : (MODE == 1) ? g_hh : g_midh;
    const __nv_bfloat16* __restrict__ Al = (MODE == 0) ? g_xal : (MODE == 1) ? g_hl : g_midl;
    const __nv_bfloat16* __restrict__ Bh = (MODE == 0) ? g_Wh1 : (MODE == 1) ? g_Wh2 : g_Wh3;
    const __nv_bfloat16* __restrict__ Bl = (MODE == 0) ? g_Wl1 : (MODE == 1) ? g_Wl2 : g_Wl3;

    extern __shared__ char smem_raw[];
    char* sm = (char*)(((uintptr_t)smem_raw + 1023) & ~(uintptr_t)1023);
    const uint32_t sbase = smem_u32(sm);

    const int tid   = threadIdx.x;
    const int lane  = tid & 31;
    const int wid   = tid >> 5;
    const int warpM = wid & 3;           // 4 m-warps (32 rows each)
    const int warpN = wid >> 2;          // 2 n-warps (64 cols each)
    const int m0 = blockIdx.y * 128;
    const int n0 = blockIdx.x * 128;

    // ldmatrix per-lane addressing (SW128: byte = row*128 + ((chunk ^ (row&7))<<4))
    const int rA   = warpM * 32 + (lane & 15);                 // + tm*16
    const int cbA  = lane >> 4;
    const int swA  = rA & 7;                                   // invariant of tm
    const int rB   = warpN * 64 + ((lane >> 4) << 3) + (lane & 7);  // + tp*16
    const int cbB  = (lane >> 3) & 1;
    const int swB  = rB & 7;                                   // = lane&7

    // stage loader
    auto load_stage = [&](int stg, int kc) {
        const uint32_t sb = sbase + stg * 65536;
        const __nv_bfloat16* pAh = Ah + (size_t)m0 * K + kc * 64;
        const __nv_bfloat16* pAl = Al + (size_t)m0 * K + kc * 64;
        const __nv_bfloat16* pBh = Bh + (size_t)n0 * K + kc * 64;
        const __nv_bfloat16* pBl = Bl + (size_t)n0 * K + kc * 64;
        #pragma unroll
        for (int i = tid; i < 1024; i += 256) {
            const int r = i >> 3, c = i & 7;
            const uint32_t d = (uint32_t)(r * 128 + ((c ^ (r & 7)) << 4));
            const size_t go = (size_t)r * K + c * 8;
            CP16(sb +         d, (const char*)(pAh + go));
            CP16(sb + 16384 + d, (const char*)(pAl + go));
            CP16(sb + 32768 + d, (const char*)(pBh + go));
            CP16(sb + 49152 + d, (const char*)(pBl + go));
        }
    };

    float acc[2][8][4];
    #pragma unroll
    for (int a = 0; a < 2; a++)
        #pragma unroll
        for (int b = 0; b < 8; b++)
            #pragma unroll
            for (int c = 0; c < 4; c++) acc[a][b][c] = 0.f;

    // prologue: fill 3 stages (NKC >= 4 always)
    load_stage(0, 0); CP_COMMIT();
    load_stage(1, 1); CP_COMMIT();
    load_stage(2, 2); CP_COMMIT();

    for (int kc = 0; kc < NKC; kc++) {
        CP_WAIT2();
        __syncthreads();
        const int stg = kc % 3;
        const uint32_t sAh = sbase + stg * 65536;
        const uint32_t sAl = sAh + 16384;
        const uint32_t sBh = sAh + 32768;
        const uint32_t sBl = sAh + 49152;

        #pragma unroll
        for (int ks = 0; ks < 4; ks++) {
            uint32_t ah[2][4], al[2][4], bh[4][4], bl[4][4];
            const int chA = ((ks * 2 + cbA) ^ swA) << 4;
            #pragma unroll
            for (int tm = 0; tm < 2; tm++) {
                const uint32_t ro = (uint32_t)((rA + tm * 16) * 128) + chA;
                ldsm4(ah[tm], sAh + ro);
                ldsm4(al[tm], sAl + ro);
            }
            const int chB = ((ks * 2 + cbB) ^ swB) << 4;
            #pragma unroll
            for (int tp = 0; tp < 4; tp++) {
                const uint32_t ro = (uint32_t)((rB + tp * 16) * 128) + chB;
                ldsm4(bh[tp], sBh + ro);
                ldsm4(bl[tp], sBl + ro);
            }
            #pragma unroll
            for (int tm = 0; tm < 2; tm++)
                #pragma unroll
                for (int tp = 0; tp < 4; tp++)
                    #pragma unroll
                    for (int j = 0; j < 2; j++) {
                        float* d = acc[tm][tp * 2 + j];
                        mma16816(d, ah[tm], &bh[tp][j * 2]);   // Ah*Bh
                        mma16816(d, ah[tm], &bl[tp][j * 2]);   // Ah*Bl
                        mma16816(d, al[tm], &bh[tp][j * 2]);   // Al*Bh
                    }
        }
        __syncthreads();
        const int nk = kc + 3;
        if (nk < NKC) load_stage(stg, nk);
        CP_COMMIT();
    }

    // ---- epilogue: fragment layout d0,d1 -> (row g, col 2t,2t+1); d2,d3 -> row g+8
    const int g = lane >> 2, t = lane & 3;
    #pragma unroll
    for (int tm = 0; tm < 2; tm++) {
        const int row0 = m0 + warpM * 32 + tm * 16 + g;
        const int row1 = row0 + 8;
        #pragma unroll
        for (int nt = 0; nt < 8; nt++) {
            const int col = n0 + warpN * 64 + nt * 8 + t * 2;
            const float* d = acc[tm][nt];
            if (MODE == 0) {
                const float* bp0 = g_biasJ + (row0 % 17) * 256;
                const float* bp1 = g_biasJ + (row1 % 17) * 256;
                float2 v0, v1;
                v0.x = fmaxf(d[0] + bp0[col], 0.f);
                v0.y = fmaxf(d[1] + bp0[col + 1], 0.f);
                v1.x = fmaxf(d[2] + bp1[col], 0.f);
                v1.y = fmaxf(d[3] + bp1[col + 1], 0.f);
                *(float2*)&g_h[(size_t)row0 * 256 + col] = v0;
                *(float2*)&g_h[(size_t)row1 * 256 + col] = v1;
            } else if (MODE == 1) {
                const float b0 = biasp[col], b1 = biasp[col + 1];
                float v00 = fmaxf(d[0] + b0, 0.f), v01 = fmaxf(d[1] + b1, 0.f);
                float v10 = fmaxf(d[2] + b0, 0.f), v11 = fmaxf(d[3] + b1, 0.f);
                float h00 = __bfloat162float(__float2bfloat16(v00));
                float h01 = __bfloat162float(__float2bfloat16(v01));
                float h10 = __bfloat162float(__float2bfloat16(v10));
                float h11 = __bfloat162float(__float2bfloat16(v11));
                *(uint32_t*)&g_midh[(size_t)row0 * 512 + col] = pack_bf2(h00, h01);
                *(uint32_t*)&g_midl[(size_t)row0 * 512 + col] = pack_bf2(v00 - h00, v01 - h01);
                *(uint32_t*)&g_midh[(size_t)row1 * 512 + col] = pack_bf2(h10, h11);
                *(uint32_t*)&g_midl[(size_t)row1 * 512 + col] = pack_bf2(v10 - h10, v11 - h11);
            } else {
                const float b0 = biasp[col], b1 = biasp[col + 1];
                if (row0 < R_ROWS) {
                    float2 v; v.x = d[0] + b0; v.y = d[1] + b1;
                    *(float2*)&Cp[(size_t)row0 * 256 + col] = v;
                }
                if (row1 < R_ROWS) {
                    float2 v; v.x = d[2] + b0; v.y = d[3] + b1;
                    *(float2*)&Cp[(size_t)row1 * 256 + col] = v;
                }
            }
        }
    }
    (void)CST;
}

// ---------------------------------------------------------------------------
// BN stats + finalize
// ---------------------------------------------------------------------------
__global__ void stats_kernel()
{
    const int c = threadIdx.x;
    size_t r0 = (size_t)blockIdx.x * STATS_CHUNK;
    size_t r1 = r0 + STATS_CHUNK;
    if (r1 > R_ROWS) r1 = R_ROWS;
    float s = 0.f, ss = 0.f;
    #pragma unroll 4
    for (size_t r = r0; r < r1; r++) {
        float v = g_h[r * 256 + c];
        s += v; ss += v * v;
    }
    g_psum[blockIdx.x * 256 + c] = s;
    g_pss [blockIdx.x * 256 + c] = ss;
}

__global__ void finalize_kernel(const float* __restrict__ bn_gamma,
                                const float* __restrict__ bn_beta)
{
    const int c = threadIdx.x;
    float s = 0.f, ss = 0.f;
    for (int b = 0; b < NB_STATS; b++) { s += g_psum[b * 256 + c]; ss += g_pss[b * 256 + c]; }
    const float inv = 1.f / (float)R_ROWS;
    float mean = s * inv;
    float var  = ss * inv - mean * mean;
    float sc = bn_gamma[c] * rsqrtf(var + 1e-5f);
    g_scale[c] = sc;
    g_shift[c] = bn_beta[c] - mean * sc;
}

// ---------------------------------------------------------------------------
// norm: BN affine + LayerNorm, warp per row; writes bf16 hi/lo for GEMM2.
// ---------------------------------------------------------------------------
__global__ void norm_kernel(const float* __restrict__ ln_g,
                            const float* __restrict__ ln_b)
{
    const int row  = blockIdx.x * 8 + (threadIdx.x >> 5);
    const int lane = threadIdx.x & 31;
    if (row >= R_ROWS) return;
    const float* rp = g_h + (size_t)row * 256;
    const int c0 = lane * 8;

    float4 v0 = *(const float4*)&rp[c0];
    float4 v1 = *(const float4*)&rp[c0 + 4];
    float4 s0 = *(const float4*)&g_scale[c0];
    float4 s1 = *(const float4*)&g_scale[c0 + 4];
    float4 h0 = *(const float4*)&g_shift[c0];
    float4 h1 = *(const float4*)&g_shift[c0 + 4];

    float w[8];
    w[0] = v0.x * s0.x + h0.x; w[1] = v0.y * s0.y + h0.y;
    w[2] = v0.z * s0.z + h0.z; w[3] = v0.w * s0.w + h0.w;
    w[4] = v1.x * s1.x + h1.x; w[5] = v1.y * s1.y + h1.y;
    w[6] = v1.z * s1.z + h1.z; w[7] = v1.w * s1.w + h1.w;

    float sum = 0.f, ssq = 0.f;
    #pragma unroll
    for (int i = 0; i < 8; i++) { sum += w[i]; ssq += w[i] * w[i]; }
    #pragma unroll
    for (int o = 16; o > 0; o >>= 1) {
        sum += __shfl_xor_sync(0xFFFFFFFFu, sum, o);
        ssq += __shfl_xor_sync(0xFFFFFFFFu, ssq, o);
    }
    const float mean = sum * (1.f / 256.f);
    const float var  = ssq * (1.f / 256.f) - mean * mean;
    const float rs   = rsqrtf(var + 1e-5f);

    float4 g0 = *(const float4*)&ln_g[c0];
    float4 g1 = *(const float4*)&ln_g[c0 + 4];
    float4 t0 = *(const float4*)&ln_b[c0];
    float4 t1 = *(const float4*)&ln_b[c0 + 4];
    float gg[8] = {g0.x, g0.y, g0.z, g0.w, g1.x, g1.y, g1.z, g1.w};
    float bb[8] = {t0.x, t0.y, t0.z, t0.w, t1.x, t1.y, t1.z, t1.w};

    float hf[8], lf[8];
    #pragma unroll
    for (int i = 0; i < 8; i++) {
        float o = (w[i] - mean) * rs * gg[i] + bb[i];
        hf[i] = __bfloat162float(__float2bfloat16(o));
        lf[i] = o - hf[i];
    }
    uint4 ph, pl;
    ph.x = pack_bf2(hf[0], hf[1]); ph.y = pack_bf2(hf[2], hf[3]);
    ph.z = pack_bf2(hf[4], hf[5]); ph.w = pack_bf2(hf[6], hf[7]);
    pl.x = pack_bf2(lf[0], lf[1]); pl.y = pack_bf2(lf[2], lf[3]);
    pl.z = pack_bf2(lf[4], lf[5]); pl.w = pack_bf2(lf[6], lf[7]);
    *(uint4*)&g_hh[(size_t)row * 256 + c0] = ph;
    *(uint4*)&g_hl[(size_t)row * 256 + c0] = pl;
}

// ---------------------------------------------------------------------------
// launch
// ---------------------------------------------------------------------------
#define SMEM_DYN (1024 + 3 * 65536)   // align slack + 3 stages x 64KB

extern "C" void kernel_launch(void* const* d_in, const int* in_sizes, int n_in,
                              void* d_out, int out_size)
{
    const float* x    = (const float*)d_in[0];
    const float* adj  = (const float*)d_in[1];
    const float* w1   = (const float*)d_in[2];
    const float* b1   = (const float*)d_in[3];
    const float* w2   = (const float*)d_in[4];
    const float* b2   = (const float*)d_in[5];
    const float* bn_g = (const float*)d_in[6];
    const float* bn_b = (const float*)d_in[7];
    const float* ln_g = (const float*)d_in[8];
    const float* ln_b = (const float*)d_in[9];
    const float* mw1  = (const float*)d_in[10];
    const float* mb1  = (const float*)d_in[11];
    const float* mw2  = (const float*)d_in[12];
    const float* mb2  = (const float*)d_in[13];
    float* out = (float*)d_out;

    cudaFuncSetAttribute(hmma_gemm_kernel<0>, cudaFuncAttributeMaxDynamicSharedMemorySize, SMEM_DYN);
    cudaFuncSetAttribute(hmma_gemm_kernel<1>, cudaFuncAttributeMaxDynamicSharedMemorySize, SMEM_DYN);
    cudaFuncSetAttribute(hmma_gemm_kernel<2>, cudaFuncAttributeMaxDynamicSharedMemorySize, SMEM_DYN);

    prep_w_kernel<<<128, 256>>>(w1, w2, mw1, mw2);
    prep_bias_kernel<<<1, 256>>>(b1, b2, adj);
    agg_kernel<<<NFRM, 256>>>(x, adj);

    hmma_gemm_kernel<0><<<dim3(2, MTILES), 256, SMEM_DYN>>>(nullptr, nullptr);

    stats_kernel<<<NB_STATS, 256>>>();
    finalize_kernel<<<1, 256>>>(bn_g, bn_b);
    norm_kernel<<<(R_ROWS + 7) / 8, 256>>>(ln_g, ln_b);

    hmma_gemm_kernel<1><<<dim3(4, MTILES), 256, SMEM_DYN>>>(mb1, nullptr);
    hmma_gemm_kernel<2><<<dim3(2, MTILES), 256, SMEM_DYN>>>(mb2, out);
}